// round 10
// baseline (speedup 1.0000x reference)
#include <cuda_runtime.h>

#define BSZ   1024
#define TLEN  64
#define SDIM  30
#define DDIM  200
#define HDIM  200
#define EDIM  1024
#define ADIM  6

typedef unsigned long long ull;

// ---------------------------------------------------------------------------
// Device scratch
// ---------------------------------------------------------------------------
__device__ float g_eo[(size_t)BSZ * TLEN * HDIM];   // embed @ w_obs1[200:] + b_obs1

// k-quad packed weights (float4 = 4 consecutive k values for one output col)
__device__ float4 g_gru4[6 * 50 * 200];  // [st][kq][c]; st: Wz,Wr,Wh,Uz,Ur,Uh
__device__ float4 g_p4[2 * 50 * 200];    // [mat][kq][c]; mat: img2, obs1d
__device__ float4 g_i14[9 * 200];        // img1 [kq][c], K=36
__device__ float4 g_h4[4 * 50 * 30];     // heads [h][kq][s]
// eo weights, k-pair interleaved: float idx ((kp*200 + c)*2 + p), kp 0..511
__device__ ull    g_wep[102400];

// ---------------------------------------------------------------------------
// Helpers
// ---------------------------------------------------------------------------
__device__ __forceinline__ ull fma2(ull a, ull b, ull c) {
    ull d;
    asm("fma.rn.f32x2 %0, %1, %2, %3;" : "=l"(d) : "l"(a), "l"(b), "l"(c));
    return d;
}
__device__ __forceinline__ float sum2(ull a) {
    float2 f;
    asm("mov.b64 {%0, %1}, %2;" : "=f"(f.x), "=f"(f.y) : "l"(a));
    return f.x + f.y;
}
__device__ __forceinline__ ulonglong2 ldg2(const float4* p) {
    return __ldg(reinterpret_cast<const ulonglong2*>(p));
}
__device__ __forceinline__ ulonglong2 lds2(const float* p) {
    return *reinterpret_cast<const ulonglong2*>(p);
}
__device__ __forceinline__ float rcpa(float x) {
    float r;
    asm("rcp.approx.f32 %0, %1;" : "=f"(r) : "f"(x));
    return r;
}
__device__ __forceinline__ float elu1(float v) {
    return v > 0.f ? v : (__expf(v) - 1.f);
}
__device__ __forceinline__ float softplus1(float x) {
    return fmaxf(x, 0.f) + __logf(1.f + __expf(-fabsf(x)));
}
__device__ __forceinline__ float sigmoid1(float x) {
    return rcpa(1.f + __expf(-x));
}
__device__ __forceinline__ void cp16(void* s, const void* g) {
    unsigned ss = (unsigned)__cvta_generic_to_shared(s);
    asm volatile("cp.async.ca.shared.global [%0], [%1], 16;" :: "r"(ss), "l"(g) : "memory");
}
#define CP_COMMIT() asm volatile("cp.async.commit_group;" ::: "memory")
#define CP_WAIT1()  asm volatile("cp.async.wait_group 1;" ::: "memory")
#define CP_WAIT0()  asm volatile("cp.async.wait_group 0;" ::: "memory")

// ---------------------------------------------------------------------------
// Repack kernel: k-quad layouts + g_wep
// ---------------------------------------------------------------------------
__global__ void repack_kernel(const float* __restrict__ w_img1,
                              const float* __restrict__ gru_w,
                              const float* __restrict__ gru_u,
                              const float* __restrict__ w_img2,
                              const float* __restrict__ w_obs1,
                              const float* __restrict__ w_omean,
                              const float* __restrict__ w_ostd,
                              const float* __restrict__ w_imean,
                              const float* __restrict__ w_istd) {
    int i = blockIdx.x * 256 + threadIdx.x;
    if (i < 240000) {                       // GRU 6 streams
        int f = i & 3, q = i >> 2;
        int st = q / 10000, rem = q % 10000, kq = rem / 200, cc = rem % 200;
        int k = 4 * kq + f;
        float v = (st < 3) ? gru_w[k * 600 + st * 200 + cc]
                           : gru_u[k * 600 + (st - 3) * 200 + cc];
        ((float*)g_gru4)[i] = v;
    } else if (i < 320000) {                // img2 / obs1d
        int j = i - 240000;
        int f = j & 3, q = j >> 2;
        int mat = q / 10000, rem = q % 10000, kq = rem / 200, cc = rem % 200;
        int k = 4 * kq + f;
        ((float*)g_p4)[j] = (mat == 0) ? w_img2[k * 200 + cc] : w_obs1[k * 200 + cc];
    } else if (i < 327200) {                // img1
        int j = i - 320000;
        int f = j & 3, q = j >> 2;
        int kq = q / 200, cc = q % 200;
        int k = 4 * kq + f;
        ((float*)g_i14)[j] = w_img1[k * 200 + cc];
    } else if (i < 351200) {                // heads
        int j = i - 327200;
        int f = j & 3, q = j >> 2;
        int h = q / 1500, rem = q % 1500, kq = rem / 30, s = rem % 30;
        int k = 4 * kq + f;
        const float* src = (h == 0) ? w_omean : (h == 1) ? w_ostd
                         : (h == 2) ? w_imean : w_istd;
        ((float*)g_h4)[j] = src[k * 30 + s];
    } else if (i < 556000) {                // eo weights (embed rows of w_obs1)
        int j = i - 351200;                 // (kp*200+c)*2 + p
        int p = j & 1, q = j >> 1;
        int c = q % 200, kp = q / 200;
        ((float*)g_wep)[j] = w_obs1[(size_t)(200 + 2 * kp + p) * 200 + c];
    }
}

// ---------------------------------------------------------------------------
// Kernel 1: eo GEMM, cp.async 3-stage pipeline, 1 sync per chunk.
// ---------------------------------------------------------------------------
__global__ __launch_bounds__(320, 1)
void eo_gemm_kernel(const float* __restrict__ embed,
                    const float* __restrict__ b_obs1) {
    __shared__ __align__(16) float sbuf[3 * 8448];

    const int tid = threadIdx.x;
    const int tx = tid % 40;
    const int ty = tid / 40;
    const int m0 = blockIdx.x * 64;

    ull acc[8][5];
#pragma unroll
    for (int r = 0; r < 8; r++)
#pragma unroll
        for (int j = 0; j < 5; j++) acc[r][j] = 0ull;

    auto issue_chunk = [&](int cc) {
        const int k0 = cc * 32;
        float* dst = sbuf + (cc % 3) * 8448;
        for (int i = tid; i < 512; i += 320) {
            int r = i >> 3, q = i & 7;
            cp16(dst + r * 32 + q * 4,
                 embed + (size_t)(m0 + r) * 1024 + k0 + q * 4);
        }
        const float* wsrc = (const float*)g_wep + (size_t)(k0 >> 1) * 400;
        float* wdst = dst + 2048;
        for (int i = tid; i < 1600; i += 320) {
            cp16(wdst + i * 4, wsrc + i * 4);
        }
        CP_COMMIT();
    };

    issue_chunk(0);
    issue_chunk(1);

    for (int c = 0; c < 32; c++) {
        if (c < 31) { CP_WAIT1(); } else { CP_WAIT0(); }
        __syncthreads();
        if (c + 2 < 32) issue_chunk(c + 2);

        const float* bs = sbuf + (c % 3) * 8448;
        const ull* as_u = (const ull*)bs;
        const ull* ws_u = (const ull*)(bs + 2048);
#pragma unroll
        for (int kp = 0; kp < 16; kp++) {
            ull wv[5];
#pragma unroll
            for (int j = 0; j < 5; j++) wv[j] = ws_u[kp * 200 + tx * 5 + j];
#pragma unroll
            for (int r = 0; r < 8; r++) {
                ull av = as_u[(ty * 8 + r) * 16 + kp];
#pragma unroll
                for (int j = 0; j < 5; j++) acc[r][j] = fma2(av, wv[j], acc[r][j]);
            }
        }
        __syncthreads();
    }

#pragma unroll
    for (int r = 0; r < 8; r++) {
        int m = m0 + ty * 8 + r;
#pragma unroll
        for (int j = 0; j < 5; j++) {
            int cc = tx * 5 + j;
            g_eo[(size_t)m * 200 + cc] = sum2(acc[r][j]) + b_obs1[cc];
        }
    }
}

// ---------------------------------------------------------------------------
// Kernel 2: persistent recurrent kernel, zero weight duplication.
// 128 CTAs x 8 rows, 800 threads, 8 barriers/step.
// P2: tid -> (side, khalf, c); 3 streams x 8 rows x 100 k per thread.
// P4: tid -> (mat, khalf, c);  8 rows x 100 k per thread.
// P5: tid -> (head, kquarter, s); 8 rows x ~50 k per thread.
// ---------------------------------------------------------------------------
__global__ __launch_bounds__(800, 1)
void rssm_recur_kernel(const float* __restrict__ action,
                       const float* __restrict__ noise_prior,
                       const float* __restrict__ noise_post,
                       const float* __restrict__ b_img1,
                       const float* __restrict__ gru_b,
                       const float* __restrict__ gru_rb,
                       const float* __restrict__ b_img2,
                       const float* __restrict__ b_imean,
                       const float* __restrict__ b_istd,
                       const float* __restrict__ b_omean,
                       const float* __restrict__ b_ostd,
                       float* __restrict__ out) {
    __shared__ __align__(16) float sm[19640];
    float* s_in  = sm;            // [8][40]                               320
    float* det0  = sm + 320;      // [8][200]
    float* det1  = sm + 1920;     // [8][200]
    float* s_x   = sm + 3520;     // [8][200]  img1 out, later x2
    float* s_xo  = sm + 5120;     // [8][200]
    float* s_eo  = sm + 6720;     // [8][200]
    float* s_scr = sm + 8320;     // scratch: P2 partials/finals, P4, P5  9600
    float* s_b1  = sm + 17920;    // [200]
    float* s_b2  = sm + 18120;    // [200]
    float* s_gb  = sm + 18320;    // [6][200]
    float* s_hb  = sm + 19520;    // [4][30]

    const int tid = threadIdx.x;
    const int b0 = blockIdx.x * 8;

    // ---- P2/P4 mapping: (group, khalf, c) ----
    const int cP   = tid % 200;
    const int khP  = (tid / 200) & 1;          // k-half
    const int sideP = tid / 400;               // P2: 0=x-side, 1=d-side; P4: mat
    const float4* wp2 = g_gru4 + sideP * 30000 + khP * 25 * 200 + cP;
    const float4* wp4 = g_p4 + sideP * 10000 + khP * 25 * 200 + cP;

    // ---- P5a mapping (tid < 480): head h, quarter q, col s ----
    const int hP5 = tid / 120;
    const int qP5 = (tid % 120) / 30;
    const int sP5 = tid % 30;
    const int q_start = (qP5 < 2) ? 13 * qP5 : 26 + 12 * (qP5 - 2);
    const int q_len   = (qP5 < 2) ? 13 : 12;
    const float4* wp5 = g_h4 + hP5 * 1500 + q_start * 30 + sP5;

    // ---- P5b mapping (tid < 480): pair p, row r, col s ----
    const int pB = tid / 240;
    const int rB = (tid % 240) / 30;
    const int sB = tid % 30;
    const float* nptr = (pB ? noise_prior : noise_post)
                        + (size_t)(b0 + rB) * SDIM + sB;
    float* optr = out + (size_t)(b0 + rB) * TLEN * 580 + (pB ? 290 : 0) + sB;

    // ---- init ----
    if (tid < 200) {
        s_b1[tid] = b_img1[tid];
        s_b2[tid] = b_img2[tid];
    }
    for (int i = tid; i < 1200; i += 800) {
        int st = i / 200, cc = i % 200;
        s_gb[i] = (st < 3) ? gru_b[st * 200 + cc] : gru_rb[(st - 3) * 200 + cc];
    }
    if (tid < 120) {
        int h = tid / 30, s = tid % 30;
        s_hb[tid] = (h == 0) ? b_omean[s] : (h == 1) ? b_ostd[s]
                  : (h == 2) ? b_imean[s] : b_istd[s];
    }
    for (int i = tid; i < 320; i += 800) s_in[i] = 0.f;
    for (int i = tid; i < 1600; i += 800) det0[i] = 0.f;
    if (tid < 48) {
        int r = tid / 6, j = tid % 6;
        s_in[r * 40 + 30 + j] = action[(size_t)(b0 + r) * (TLEN * ADIM) + j];
    }
    float* pd = det0;
    float* pn = det1;
    __syncthreads();

    for (int t = 0; t < TLEN; ++t) {
        // ====== P1: x = elu([stoch,action]@W1 + b)  |  eo loads =============
        if (tid < 400) {
            const int c = tid % 200, rh = tid / 200;
            ull acc[4];
#pragma unroll
            for (int j = 0; j < 4; j++) acc[j] = 0ull;
#pragma unroll
            for (int kq = 0; kq < 9; kq++) {
                ulonglong2 w = ldg2(g_i14 + kq * 200 + c);
#pragma unroll
                for (int j = 0; j < 4; j++) {
                    ulonglong2 v = lds2(s_in + (rh * 4 + j) * 40 + 4 * kq);
                    acc[j] = fma2(v.x, w.x, acc[j]);
                    acc[j] = fma2(v.y, w.y, acc[j]);
                }
            }
            float bb = s_b1[c];
#pragma unroll
            for (int j = 0; j < 4; j++)
                s_x[(rh * 4 + j) * 200 + c] = elu1(sum2(acc[j]) + bb);
        } else if (tid >= 600) {
            int t2 = tid - 600;
#pragma unroll
            for (int i = 0; i < 8; i++) {
                int e = t2 + 200 * i;
                int r = e / 200, cc = e - r * 200;
                s_eo[e] = __ldg(&g_eo[((size_t)(b0 + r) * TLEN + t) * 200 + cc]);
            }
        }
        __syncthreads();                              // b1

        // ====== P2a: GRU partials, 3 streams x 8 rows x 100k ===============
        float xf[3][8];   // kh1 finals / partial sums
        {
            const float* src = sideP ? pd : s_x;
            const int kb = khP * 25;
            ull a0[8], a1[8], a2[8];
#pragma unroll
            for (int r = 0; r < 8; r++) { a0[r] = 0; a1[r] = 0; a2[r] = 0; }
            ulonglong2 w0 = ldg2(wp2);
            ulonglong2 w1 = ldg2(wp2 + 10000);
            ulonglong2 w2 = ldg2(wp2 + 20000);
            for (int kq = 0; kq < 25; kq++) {
                const int kn = (kq < 24) ? kq + 1 : 24;
                ulonglong2 n0 = ldg2(wp2 + kn * 200);
                ulonglong2 n1 = ldg2(wp2 + 10000 + kn * 200);
                ulonglong2 n2 = ldg2(wp2 + 20000 + kn * 200);
#pragma unroll
                for (int r = 0; r < 8; r++) {
                    ulonglong2 v = lds2(src + r * 200 + 4 * (kb + kq));
                    a0[r] = fma2(v.x, w0.x, a0[r]);
                    a0[r] = fma2(v.y, w0.y, a0[r]);
                    a1[r] = fma2(v.x, w1.x, a1[r]);
                    a1[r] = fma2(v.y, w1.y, a1[r]);
                    a2[r] = fma2(v.x, w2.x, a2[r]);
                    a2[r] = fma2(v.y, w2.y, a2[r]);
                }
                w0 = n0; w1 = n1; w2 = n2;
            }
            if (khP == 0) {
                float* dst = s_scr + sideP * 4800 + cP;
#pragma unroll
                for (int r = 0; r < 8; r++) {
                    dst[r * 200]        = sum2(a0[r]);
                    dst[1600 + r * 200] = sum2(a1[r]);
                    dst[3200 + r * 200] = sum2(a2[r]);
                }
            } else {
#pragma unroll
                for (int r = 0; r < 8; r++) {
                    xf[0][r] = sum2(a0[r]);
                    xf[1][r] = sum2(a1[r]);
                    xf[2][r] = sum2(a2[r]);
                }
            }
        }
        __syncthreads();                              // b2

        // ====== P2b: khalf1 finalize; d-side stores finals ==================
        if (khP == 1) {
            const float* part = s_scr + sideP * 4800 + cP;
            float bz = s_gb[(sideP * 3 + 0) * 200 + cP];
            float br = s_gb[(sideP * 3 + 1) * 200 + cP];
            float bh = s_gb[(sideP * 3 + 2) * 200 + cP];
#pragma unroll
            for (int r = 0; r < 8; r++) {
                xf[0][r] += part[r * 200] + bz;
                xf[1][r] += part[1600 + r * 200] + br;
                xf[2][r] += part[3200 + r * 200] + bh;
            }
            if (sideP) {
                float* dst = s_scr + 4800 + cP;
#pragma unroll
                for (int r = 0; r < 8; r++) {
                    dst[r * 200]        = xf[0][r];
                    dst[1600 + r * 200] = xf[1][r];
                    dst[3200 + r * 200] = xf[2][r];
                }
            }
        }
        __syncthreads();                              // b3

        // ====== P3: gates by x-side khalf1 (200 threads, 8 rows each) ======
        if (sideP == 0 && khP == 1) {
            const float* dg = s_scr + 4800 + cP;
#pragma unroll
            for (int r = 0; r < 8; r++) {
                int idx = r * 200 + cP;
                float z  = sigmoid1(xf[0][r] + dg[r * 200]);
                float rg = sigmoid1(xf[1][r] + dg[1600 + r * 200]);
                float a  = xf[2][r] + rg * dg[3200 + r * 200];
                float e2 = __expf(2.f * a);
                float th = 1.f - 2.f * rcpa(e2 + 1.f);
                float dn = z * pd[idx] + (1.f - z) * th;
                pn[idx] = dn;
                float* orow = out + ((size_t)(b0 + r) * TLEN + t) * 580;
                orow[90 + cP]  = dn;
                orow[380 + cP] = dn;
            }
        }
        __syncthreads();                              // b4

        // ====== P4a: x2/xo partials, 8 rows x 100k per thread ==============
        float f4[8];
        {
            const int kb = khP * 25;
            ull acc[8];
#pragma unroll
            for (int r = 0; r < 8; r++) acc[r] = 0ull;
            ulonglong2 w = ldg2(wp4);
            for (int kq = 0; kq < 25; kq++) {
                const int kn = (kq < 24) ? kq + 1 : 24;
                ulonglong2 n = ldg2(wp4 + kn * 200);
#pragma unroll
                for (int r = 0; r < 8; r++) {
                    ulonglong2 v = lds2(pn + r * 200 + 4 * (kb + kq));
                    acc[r] = fma2(v.x, w.x, acc[r]);
                    acc[r] = fma2(v.y, w.y, acc[r]);
                }
                w = n;
            }
            if (khP == 0) {
                float* dst = s_scr + sideP * 1600 + cP;
#pragma unroll
                for (int r = 0; r < 8; r++) dst[r * 200] = sum2(acc[r]);
            } else {
#pragma unroll
                for (int r = 0; r < 8; r++) f4[r] = sum2(acc[r]);
            }
        }
        __syncthreads();                              // b5

        // ====== P4b: khalf1 finalize -> s_x / s_xo ==========================
        if (khP == 1) {
            const float* part = s_scr + sideP * 1600 + cP;
            if (sideP == 0) {
                float bb = s_b2[cP];
#pragma unroll
                for (int r = 0; r < 8; r++)
                    s_x[r * 200 + cP] = elu1(f4[r] + part[r * 200] + bb);
            } else {
#pragma unroll
                for (int r = 0; r < 8; r++)
                    s_xo[r * 200 + cP] = elu1(f4[r] + part[r * 200] + s_eo[r * 200 + cP]);
            }
        }
        __syncthreads();                              // b6

        // ====== P5a: head partials (480 thr), quarter-k each ===============
        if (tid < 480) {
            const float* srcb = (hP5 < 2) ? s_xo : s_x;
            ull acc[8];
#pragma unroll
            for (int r = 0; r < 8; r++) acc[r] = 0ull;
            ulonglong2 w = ldg2(wp5);
            for (int i = 0; i < q_len; i++) {
                const int in = (i < q_len - 1) ? i + 1 : i;
                ulonglong2 n = ldg2(wp5 + in * 30);
#pragma unroll
                for (int r = 0; r < 8; r++) {
                    ulonglong2 v = lds2(srcb + r * 200 + 4 * (q_start + i));
                    acc[r] = fma2(v.x, w.x, acc[r]);
                    acc[r] = fma2(v.y, w.y, acc[r]);
                }
                w = n;
            }
            float* dst = s_scr + qP5 * 960 + hP5 * 240 + sP5;
#pragma unroll
            for (int r = 0; r < 8; r++) dst[r * 30] = sum2(acc[r]);
        }
        __syncthreads();                              // b7

        // ====== P5b: samples + carry (480 thr) + action prefetch ===========
        if (tid < 480) {
            float nz = __ldg(nptr + (size_t)t * (BSZ * SDIM));
            const float* pm = s_scr + (2 * pB) * 240 + rB * 30 + sB;
            const float* ps = s_scr + (2 * pB + 1) * 240 + rB * 30 + sB;
            float mean = pm[0] + pm[960] + pm[1920] + pm[2880] + s_hb[2 * pB * 30 + sB];
            float sv   = ps[0] + ps[960] + ps[1920] + ps[2880] + s_hb[(2 * pB + 1) * 30 + sB];
            float sdev = softplus1(sv);
            if (pB) sdev += 0.1f;
            float stoch = mean + sdev * nz;

            float* op = optr + (size_t)t * 580;
            op[0]  = mean;
            op[30] = sdev;
            op[60] = stoch;
            if (pB == 0) s_in[rB * 40 + sB] = stoch;  // posterior carry
        } else if (tid >= 752 && t + 1 < TLEN) {
            int idx = tid - 752;
            int r = idx / 6, j = idx % 6;
            s_in[r * 40 + 30 + j] =
                action[(size_t)(b0 + r) * (TLEN * ADIM) + (t + 1) * ADIM + j];
        }

        { float* tmp = pd; pd = pn; pn = tmp; }
        __syncthreads();                              // b8
    }
}

// ---------------------------------------------------------------------------
// Launch
// ---------------------------------------------------------------------------
extern "C" void kernel_launch(void* const* d_in, const int* in_sizes, int n_in,
                              void* d_out, int out_size) {
    const float* embed       = (const float*)d_in[0];
    const float* action      = (const float*)d_in[1];
    const float* noise_prior = (const float*)d_in[2];
    const float* noise_post  = (const float*)d_in[3];
    const float* w_img1      = (const float*)d_in[4];
    const float* b_img1      = (const float*)d_in[5];
    const float* gru_w       = (const float*)d_in[6];
    const float* gru_u       = (const float*)d_in[7];
    const float* gru_b       = (const float*)d_in[8];
    const float* gru_rb      = (const float*)d_in[9];
    const float* w_img2      = (const float*)d_in[10];
    const float* b_img2      = (const float*)d_in[11];
    const float* w_imean     = (const float*)d_in[12];
    const float* b_imean     = (const float*)d_in[13];
    const float* w_istd      = (const float*)d_in[14];
    const float* b_istd      = (const float*)d_in[15];
    const float* w_obs1      = (const float*)d_in[16];
    const float* b_obs1      = (const float*)d_in[17];
    const float* w_omean     = (const float*)d_in[18];
    const float* b_omean     = (const float*)d_in[19];
    const float* w_ostd      = (const float*)d_in[20];
    const float* b_ostd      = (const float*)d_in[21];
    float* out = (float*)d_out;

    repack_kernel<<<(556000 + 255) / 256, 256>>>(w_img1, gru_w, gru_u, w_img2,
                                                 w_obs1, w_omean, w_ostd,
                                                 w_imean, w_istd);
    eo_gemm_kernel<<<BSZ * TLEN / 64, 320>>>(embed, b_obs1);
    rssm_recur_kernel<<<BSZ / 8, 800>>>(action, noise_prior, noise_post,
                                        b_img1, gru_b, gru_rb, b_img2,
                                        b_imean, b_istd, b_omean, b_ostd, out);
}